// round 13
// baseline (speedup 1.0000x reference)
#include <cuda_runtime.h>
#include <cuda_fp16.h>
#include <math.h>
#include <stdint.h>

// ---------------- problem constants ----------------
#define M_TOK   65536
#define KCODE   1024
#define BM      64            // tokens per CTA
#define BN      64            // codes per chunk
#define NCHUNK  16
#define GRID_MAIN 1024
#define MARGIN  0.25f

// Output layout (floats): [z_q | similarity | ids | loss]
#define SIM_OFF   8388608ULL
#define IDSG_OFF  75497472ULL
#define LOSS_OFF  75563008ULL

// ---------------- smem layout (byte offsets) ----------------
#define A_OFF      0              // z1 fp16: 64 rows x 256B = 16384 (dead after loop)
#define B_OFF      16384          // two B buffers x 16384 (dead after loop)
#define B_BUF      16384
#define STAGE_OFF  49152          // sim stage: 64 rows x 272B = 17408
#define STAGE_PITCH 272           // MULTIPLE OF 16 (R11's 264 broke float4 alignment)
#define NE_OFF     66560          // 4096
#define RE_OFF     70656          // 4096
#define NZ_OFF     74752          // 256
#define RZ_OFF     75008          // 256
#define IDS_SM     75264          // 256
#define LT_SM      75520          // 256
#define MBAR_OFF   75776          // 2 x u64
#define SMEM_BYTES 75808          // x3 CTAs = 227424 <= 228KB carveout

// post-loop overlays (regions dead after the main loop)
#define REDD_OFF   0              // 64 tok x 32 cand dists = 8192   (over A)
#define REDI_OFF   8192           // 64 tok x 32 cand idx   = 8192   (over A)
#define ZF_OFF     16384          // fp32 Z tile, 32KB               (over B0+B1)

// ---------------- device scratch ----------------
// fp16 codebook, PRE-SWIZZLED in 16KB chunk blocks (see prep_e): a linear
// cp.async.bulk lands exactly in the ldmatrix-ready swizzled layout.
__device__ __align__(16) __half g_Eb[KCODE * 128];
__device__ float g_ne[KCODE];
__device__ float g_re[KCODE];
__device__ float g_partial[GRID_MAIN];

// ---------------- PTX helpers (baseline ISA only; no 'a'-gated features) ----
__device__ __forceinline__ uint32_t smem_u32(const void* p) {
    uint32_t a;
    asm("{ .reg .u64 t; cvta.to.shared.u64 t, %1; cvt.u32.u64 %0, t; }" : "=r"(a) : "l"(p));
    return a;
}
__device__ __forceinline__ void ldsm_x4(uint32_t& r0, uint32_t& r1, uint32_t& r2, uint32_t& r3,
                                        uint32_t addr) {
    asm volatile("ldmatrix.sync.aligned.m8n8.x4.shared.b16 {%0,%1,%2,%3}, [%4];"
                 : "=r"(r0), "=r"(r1), "=r"(r2), "=r"(r3) : "r"(addr));
}
__device__ __forceinline__ void mma_f16(float* c, const uint32_t* a, const uint32_t* b) {
    asm volatile("mma.sync.aligned.m16n8k16.row.col.f32.f16.f16.f32 "
                 "{%0,%1,%2,%3}, {%4,%5,%6,%7}, {%8,%9}, {%0,%1,%2,%3};"
                 : "+f"(c[0]), "+f"(c[1]), "+f"(c[2]), "+f"(c[3])
                 : "r"(a[0]), "r"(a[1]), "r"(a[2]), "r"(a[3]), "r"(b[0]), "r"(b[1]));
}
#define MBARRIER_INIT(addr, cnt) \
    asm volatile("mbarrier.init.shared.b64 [%0], %1;" :: "r"(addr), "r"(cnt) : "memory")
#define MBARRIER_EXPECT_TX(addr, tx) \
    asm volatile("mbarrier.arrive.expect_tx.shared.b64 _, [%0], %1;" \
                 :: "r"(addr), "r"(tx) : "memory")
__device__ __forceinline__ void bulk_g2s(uint32_t sdst, const void* gsrc,
                                         uint32_t bytes, uint32_t mbar) {
    asm volatile("cp.async.bulk.shared::cluster.global.mbarrier::complete_tx::bytes "
                 "[%0], [%1], %2, [%3];"
                 :: "r"(sdst), "l"(gsrc), "r"(bytes), "r"(mbar) : "memory");
}
__device__ __forceinline__ void mbar_wait_parity(uint32_t mbar, uint32_t parity) {
    uint32_t done;
    asm volatile(
        "{\n\t.reg .pred p;\n\t"
        "mbarrier.try_wait.parity.acquire.cta.shared::cta.b64 p, [%1], %2;\n\t"
        "selp.b32 %0, 1, 0, p;\n\t}"
        : "=r"(done) : "r"(mbar), "r"(parity) : "memory");
    if (!done) {
        asm volatile(
            "{\n\t.reg .pred P1;\n\t"
            "WL_%=: \n\t"
            "mbarrier.try_wait.parity.acquire.cta.shared::cta.b64 P1, [%0], %1, 0x989680;\n\t"
            "@P1 bra.uni WD_%=;\n\t"
            "bra.uni WL_%=;\n\t"
            "WD_%=: \n\t}"
            :: "r"(mbar), "r"(parity) : "memory");
    }
}

// ---------------- codebook prep: fp16 convert + norms + pre-swizzle ---------
__global__ void prep_e(const float* __restrict__ E) {
    int row  = blockIdx.x * 8 + (threadIdx.x >> 5);
    int lane = threadIdx.x & 31;
    float4 v = reinterpret_cast<const float4*>(E)[(size_t)row * 32 + lane];
    float s = fmaf(v.x, v.x, fmaf(v.y, v.y, fmaf(v.z, v.z, v.w * v.w)));
#pragma unroll
    for (int m = 16; m; m >>= 1) s += __shfl_xor_sync(0xffffffffu, s, m);
    if (lane == 0) { g_ne[row] = s; g_re[row] = rsqrtf(s); }
    __half2 h0 = __halves2half2(__float2half_rn(v.x), __float2half_rn(v.y));
    __half2 h1 = __halves2half2(__float2half_rn(v.z), __float2half_rn(v.w));
    int c  = row >> 6;
    int rr = row & 63;
    int u  = lane >> 1;
    int h  = lane & 1;
    char* dst = (char*)g_Eb + (size_t)c * 16384 + rr * 256
              + (((u ^ (rr & 7)) & 15) << 4) + h * 8;
    uint2 val = make_uint2(*reinterpret_cast<uint32_t*>(&h0),
                           *reinterpret_cast<uint32_t*>(&h1));
    *reinterpret_cast<uint2*>(dst) = val;
}

// ---------------- main fused kernel ----------------
__global__ __launch_bounds__(256, 3)
void vq_main(const float* __restrict__ Z, const float* __restrict__ E,
             float* __restrict__ out) {
    extern __shared__ char sb[];
    const uint32_t sbase = smem_u32(sb);

    const int tid  = threadIdx.x;
    const int lane = tid & 31;
    const int warp = tid >> 5;
    const int wy   = warp >> 2;      // m half (0,1): 32 rows each
    const int wx   = warp & 3;       // n quarter (0..3): 16 codes each
    const int qrow = lane >> 2;
    const int qcol = lane & 3;
    const int m0   = blockIdx.x * BM;

    float* ne_sm = (float*)(sb + NE_OFF);
    float* re_sm = (float*)(sb + RE_OFF);
    float* nz_sm = (float*)(sb + NZ_OFF);
    float* rz_sm = (float*)(sb + RZ_OFF);
    int*   ids_sm = (int*)(sb + IDS_SM);
    float* lt_sm  = (float*)(sb + LT_SM);

    float* zq   = out;
    float* sim  = out + SIM_OFF;
    float* idsf = out + IDSG_OFF;

    // mbarrier init, then kick off bulk loads for chunks 0 and 1
    if (tid == 0) {
        MBARRIER_INIT(sbase + MBAR_OFF, 1);
        MBARRIER_INIT(sbase + MBAR_OFF + 8, 1);
    }
    __syncthreads();
    if (tid == 0) {
        MBARRIER_EXPECT_TX(sbase + MBAR_OFF, 16384u);
        bulk_g2s(sbase + B_OFF, (const char*)g_Eb, 16384u, sbase + MBAR_OFF);
        MBARRIER_EXPECT_TX(sbase + MBAR_OFF + 8, 16384u);
        bulk_g2s(sbase + B_OFF + B_BUF, (const char*)g_Eb + 16384, 16384u,
                 sbase + MBAR_OFF + 8);
    }

    // codebook norms into smem
    for (int i = tid; i < KCODE; i += 256) { ne_sm[i] = g_ne[i]; re_sm[i] = g_re[i]; }

    // A prologue: thread = (row, k-quarter of 32 dims); fp32 norm + fp16 convert
    {
        const int row = tid >> 2, kh = tid & 3;
        const float4* Zr = reinterpret_cast<const float4*>(
            Z + (size_t)(m0 + row) * 128 + kh * 32);
        float nzp = 0.f;
        uint32_t p1[16];
#pragma unroll
        for (int g = 0; g < 4; ++g) {
            float4 v0 = Zr[2 * g], v1 = Zr[2 * g + 1];
            nzp = fmaf(v0.x, v0.x, fmaf(v0.y, v0.y, fmaf(v0.z, v0.z, fmaf(v0.w, v0.w, nzp))));
            nzp = fmaf(v1.x, v1.x, fmaf(v1.y, v1.y, fmaf(v1.z, v1.z, fmaf(v1.w, v1.w, nzp))));
            __half2 h0 = __halves2half2(__float2half_rn(v0.x), __float2half_rn(v0.y));
            __half2 h1 = __halves2half2(__float2half_rn(v0.z), __float2half_rn(v0.w));
            __half2 h2 = __halves2half2(__float2half_rn(v1.x), __float2half_rn(v1.y));
            __half2 h3 = __halves2half2(__float2half_rn(v1.z), __float2half_rn(v1.w));
            p1[4 * g + 0] = *reinterpret_cast<uint32_t*>(&h0);
            p1[4 * g + 1] = *reinterpret_cast<uint32_t*>(&h1);
            p1[4 * g + 2] = *reinterpret_cast<uint32_t*>(&h2);
            p1[4 * g + 3] = *reinterpret_cast<uint32_t*>(&h3);
        }
#pragma unroll
        for (int q = 0; q < 4; ++q) {
            uint32_t u   = (uint32_t)(kh * 4 + q);
            uint32_t off = (uint32_t)row * 256u + (((u ^ (uint32_t)(row & 7))) << 4);
            *(uint4*)(sb + A_OFF + off) = make_uint4(p1[4*q], p1[4*q+1], p1[4*q+2], p1[4*q+3]);
        }
        nzp += __shfl_xor_sync(0xffffffffu, nzp, 1);
        nzp += __shfl_xor_sync(0xffffffffu, nzp, 2);
        if (kh == 0) { nz_sm[row] = nzp; rz_sm[row] = rsqrtf(nzp); }
    }
    __syncthreads();

    // per-thread row constants (4 rows: 2 mfrags x 2 halves)
    float nz4[4], rz4[4];
#pragma unroll
    for (int i = 0; i < 2; ++i)
#pragma unroll
        for (int h = 0; h < 2; ++h) {
            int ml = wy * 32 + i * 16 + qrow + 8 * h;
            nz4[i * 2 + h] = nz_sm[ml];
            rz4[i * 2 + h] = rz_sm[ml];
        }

    // per-thread TOP-2 (dist, idx) per token row
    float bd1[4], bd2[4]; int bi1[4], bi2[4];
#pragma unroll
    for (int i = 0; i < 4; ++i) { bd1[i] = 3.4e38f; bd2[i] = 3.4e38f; bi1[i] = 0; bi2[i] = 0; }

    const int sel = lane >> 3;          // 0..3 (ldmatrix address group)

#pragma unroll 1
    for (int t = 0; t < NCHUNK; ++t) {
        const uint32_t mb = sbase + MBAR_OFF + (uint32_t)(t & 1) * 8;
        mbar_wait_parity(mb, (uint32_t)((t >> 1) & 1));
        const uint32_t Bb = sbase + B_OFF + (uint32_t)(t & 1) * B_BUF;

        float acc[2][2][4];
#pragma unroll
        for (int i = 0; i < 2; ++i)
#pragma unroll
            for (int nf = 0; nf < 2; ++nf)
#pragma unroll
                for (int q = 0; q < 4; ++q) acc[i][nf][q] = 0.f;

        // single-product fp16 GEMM: z1 . e1
#pragma unroll
        for (int kk = 0; kk < 8; ++kk) {
            const uint32_t cu = (uint32_t)(kk * 2 + (sel >> 1));
            uint32_t a[2][4];
#pragma unroll
            for (int i = 0; i < 2; ++i) {
                int r = wy * 32 + i * 16 + (sel & 1) * 8 + (lane & 7);
                uint32_t addr = sbase + A_OFF + (uint32_t)r * 256u
                              + (((cu ^ (uint32_t)(r & 7))) << 4);
                ldsm_x4(a[i][0], a[i][1], a[i][2], a[i][3], addr);
            }
            int r = wx * 16 + (sel & 1) * 8 + (lane & 7);
            uint32_t addr = Bb + (uint32_t)r * 256u + (((cu ^ (uint32_t)(r & 7))) << 4);
            uint32_t b0, b1, b2, b3;
            ldsm_x4(b0, b1, b2, b3, addr);
            uint32_t bf0[2] = { b0, b2 };
            uint32_t bf1[2] = { b1, b3 };
#pragma unroll
            for (int i = 0; i < 2; ++i) {
                mma_f16(acc[i][0], a[i], bf0);
                mma_f16(acc[i][1], a[i], bf1);
            }
        }
        __syncthreads();   // B(t) consumed by all warps; stage(t-1) fully flushed
        if (t + 2 < NCHUNK && tid == 0) {     // refill freed buffer with chunk t+2
            MBARRIER_EXPECT_TX(mb, 16384u);
            bulk_g2s(Bb, (const char*)g_Eb + (size_t)(t + 2) * 16384, 16384u, mb);
        }

        // ---- epilogue: dist -> top-2 + sim into smem stage ----
#pragma unroll
        for (int nf = 0; nf < 2; ++nf) {
            const int cc = wx * 16 + nf * 8 + qcol * 2;     // chunk-local code
            const int nc = t * BN + cc;                      // global code
            float2 ne2 = *reinterpret_cast<const float2*>(ne_sm + nc);
            float2 re2 = *reinterpret_cast<const float2*>(re_sm + nc);
#pragma unroll
            for (int i = 0; i < 2; ++i) {
#pragma unroll
                for (int h = 0; h < 2; ++h) {
                    const int idx = i * 2 + h;
                    const float d0 = acc[i][nf][h * 2 + 0];
                    const float d1 = acc[i][nf][h * 2 + 1];
                    float dd0 = fmaf(-2.f, d0, nz4[idx]) + ne2.x;
                    float dd1 = fmaf(-2.f, d1, nz4[idx]) + ne2.y;
                    if (dd0 < bd2[idx]) {
                        if (dd0 < bd1[idx]) { bd2[idx]=bd1[idx]; bi2[idx]=bi1[idx];
                                              bd1[idx]=dd0; bi1[idx]=nc; }
                        else                { bd2[idx]=dd0; bi2[idx]=nc; }
                    }
                    if (dd1 < bd2[idx]) {
                        if (dd1 < bd1[idx]) { bd2[idx]=bd1[idx]; bi2[idx]=bi1[idx];
                                              bd1[idx]=dd1; bi1[idx]=nc + 1; }
                        else                { bd2[idx]=dd1; bi2[idx]=nc + 1; }
                    }
                    const int ml = wy * 32 + i * 16 + qrow + 8 * h;
                    float2 sv = make_float2(d0 * rz4[idx] * re2.x,
                                            d1 * rz4[idx] * re2.y);
                    *reinterpret_cast<float2*>(
                        sb + STAGE_OFF + ml * STAGE_PITCH + cc * 4) = sv;
                }
            }
        }
        __syncthreads();   // stage complete

        // ---- flush stage: fully-coalesced STG.128, 256B per row segment ----
        {
            const int half = lane >> 4;          // 0/1: which row of the pair
            const int col  = lane & 15;          // 16B unit within the 256B row
#pragma unroll
            for (int it = 0; it < 4; ++it) {
                const int row = it * 16 + warp * 2 + half;
                float4 v = *reinterpret_cast<const float4*>(
                    sb + STAGE_OFF + row * STAGE_PITCH + col * 16);
                *reinterpret_cast<float4*>(
                    sim + (size_t)(m0 + row) * 1024 + t * BN + col * 4) = v;
            }
        }
    }

    // ---- dump per-thread top-2 candidates into dead A region ----
    float* redD = (float*)(sb + REDD_OFF);
    int*   redI = (int*)(sb + REDI_OFF);
#pragma unroll
    for (int idx = 0; idx < 4; ++idx) {
        int i = idx >> 1, h = idx & 1;
        int tok = wy * 32 + i * 16 + qrow + 8 * h;
        int base = tok * 32 + (wx * 4 + qcol) * 2;
        redD[base] = bd1[idx];     redI[base] = bi1[idx];
        redD[base + 1] = bd2[idx]; redI[base + 1] = bi2[idx];
    }

    // ---- reload fp32 Z tile into dead B buffers ----
    {
        float4* zf = (float4*)(sb + ZF_OFF);
        const float4* Zg = reinterpret_cast<const float4*>(Z) + (size_t)m0 * 32;
#pragma unroll
        for (int i = 0; i < 8; ++i) zf[tid + 256 * i] = Zg[tid + 256 * i];
    }
    __syncthreads();

    // ---- exact fp32 refine: one thread per token ----
    if (tid < BM) {
        const int tok = tid;
        float m1 = 3.4e38f;
#pragma unroll
        for (int e = 0; e < 32; ++e) m1 = fminf(m1, redD[tok * 32 + e]);
        const float thr = m1 + MARGIN;
        const float nzt = nz_sm[tok];
        const float4* zf = (float4*)(sb + ZF_OFF) + tok * 32;
        float bestd = 3.4e38f; int besti = KCODE;
        for (int e = 0; e < 32; ++e) {
            if (redD[tok * 32 + e] <= thr) {
                const int id = redI[tok * 32 + e];
                const float4* Er = reinterpret_cast<const float4*>(E) + (size_t)id * 32;
                float dot = 0.f;
#pragma unroll
                for (int q = 0; q < 32; ++q) {
                    float4 a = zf[q], b = Er[q];
                    dot = fmaf(a.x, b.x, fmaf(a.y, b.y, fmaf(a.z, b.z, fmaf(a.w, b.w, dot))));
                }
                float de = fmaf(-2.f, dot, nzt) + ne_sm[id];   // reference association order
                if (de < bestd || (de == bestd && id < besti)) { bestd = de; besti = id; }
            }
        }
        ids_sm[tok] = besti;
        idsf[m0 + tok] = (float)besti;
        lt_sm[tok] = sqrtf(fmaxf(bestd, 0.f));   // ||z - z_q||^2 == dist_min exactly
    }
    __syncthreads();

    // z_q gather (codebook is L2-resident)
    const float4* E4  = reinterpret_cast<const float4*>(E);
    float4*       ZQ4 = reinterpret_cast<float4*>(zq);
#pragma unroll
    for (int rr = 0; rr < 8; ++rr) {
        int ml = warp * 8 + rr;
        int id = ids_sm[ml];
        ZQ4[(size_t)(m0 + ml) * 32 + lane] = E4[(size_t)id * 32 + lane];
    }

    // deterministic per-block loss partial (fixed serial order)
    if (tid == 0) {
        float s = 0.f;
        for (int i = 0; i < BM; ++i) s += lt_sm[i];
        g_partial[blockIdx.x] = s;
    }
}

// loss = 1.25 * mean ||z_e - z_q||  (deterministic tree)
__global__ void loss_final(float* __restrict__ out) {
    __shared__ float red[1024];
    int tid = threadIdx.x;
    red[tid] = g_partial[tid];
    __syncthreads();
#pragma unroll
    for (int s = 512; s > 0; s >>= 1) {
        if (tid < s) red[tid] += red[tid + s];
        __syncthreads();
    }
    if (tid == 0) out[LOSS_OFF] = 1.25f * (red[0] * (1.f / 65536.f));
}

extern "C" void kernel_launch(void* const* d_in, const int* in_sizes, int n_in,
                              void* d_out, int out_size) {
    (void)in_sizes; (void)n_in; (void)out_size;
    const float* Z = (const float*)d_in[0];   // z_e            [65536, 128]
    const float* E = (const float*)d_in[1];   // vecs_embedding [1024, 128]
    float* out = (float*)d_out;

    cudaFuncSetAttribute((const void*)vq_main,
                         cudaFuncAttributeMaxDynamicSharedMemorySize, SMEM_BYTES);

    prep_e<<<KCODE / 8, 256>>>(E);
    vq_main<<<GRID_MAIN, 256, SMEM_BYTES>>>(Z, E, out);
    loss_final<<<1, 1024>>>(out);
}

// round 14
// speedup vs baseline: 1.0082x; 1.0082x over previous
#include <cuda_runtime.h>
#include <cuda_fp16.h>
#include <math.h>
#include <stdint.h>

// ---------------- problem constants ----------------
#define M_TOK   65536
#define KCODE   1024
#define BM      64            // tokens per CTA
#define BN      64            // codes per chunk
#define NCHUNK  16
#define NBUF    3             // B prefetch ring depth
#define GRID_MAIN 1024
#define MARGIN  0.25f

// Output layout (floats): [z_q | similarity | ids | loss]
#define SIM_OFF   8388608ULL
#define IDSG_OFF  75497472ULL
#define LOSS_OFF  75563008ULL

// ---------------- smem layout (byte offsets) ----------------
#define ZF_PITCH   528            // 33x16B: 4-way (not 32-way) conflicts in refine
#define ZF_OFF     0              // fp32 Z tile: 64 x 528 = 33792 (live whole kernel)
#define A_OFF      33792          // z fp16: 64 x 256B = 16384 (dead after loop; 256-aligned)
#define B_OFF      50176          // ring: 3 x 16384 (dead after loop; 256-aligned)
#define B_BUF      16384
#define NE_OFF     99328          // 4096
#define RE_OFF     103424         // 4096
#define NZ_OFF     107520         // 256
#define RZ_OFF     107776         // 256
#define IDS_SM     108032         // 256
#define LT_SM      108288         // 256
#define MBAR_OFF   108544         // 3 x u64
#define SMEM_BYTES 108576         // x2 CTAs = 217152 <= 228KB carveout

// post-loop overlays (A region dead after main loop)
#define REDD_OFF   33792          // 64 tok x 32 cand dists = 8192
#define REDI_OFF   41984          // 64 tok x 32 cand idx   = 8192

// ---------------- device scratch ----------------
// fp16 codebook, PRE-SWIZZLED in 16KB chunk blocks (see prep_e): a linear
// cp.async.bulk lands exactly in the ldmatrix-ready swizzled layout.
__device__ __align__(16) __half g_Eb[KCODE * 128];
__device__ float g_ne[KCODE];
__device__ float g_re[KCODE];
__device__ float g_partial[GRID_MAIN];
__device__ unsigned g_done = 0;   // last-CTA counter (self-resetting each pass)

// ---------------- PTX helpers (baseline ISA only; no 'a'-gated features) ----
__device__ __forceinline__ uint32_t smem_u32(const void* p) {
    uint32_t a;
    asm("{ .reg .u64 t; cvta.to.shared.u64 t, %1; cvt.u32.u64 %0, t; }" : "=r"(a) : "l"(p));
    return a;
}
__device__ __forceinline__ void ldsm_x4(uint32_t& r0, uint32_t& r1, uint32_t& r2, uint32_t& r3,
                                        uint32_t addr) {
    asm volatile("ldmatrix.sync.aligned.m8n8.x4.shared.b16 {%0,%1,%2,%3}, [%4];"
                 : "=r"(r0), "=r"(r1), "=r"(r2), "=r"(r3) : "r"(addr));
}
__device__ __forceinline__ void mma_f16(float* c, const uint32_t* a, const uint32_t* b) {
    asm volatile("mma.sync.aligned.m16n8k16.row.col.f32.f16.f16.f32 "
                 "{%0,%1,%2,%3}, {%4,%5,%6,%7}, {%8,%9}, {%0,%1,%2,%3};"
                 : "+f"(c[0]), "+f"(c[1]), "+f"(c[2]), "+f"(c[3])
                 : "r"(a[0]), "r"(a[1]), "r"(a[2]), "r"(a[3]), "r"(b[0]), "r"(b[1]));
}
// streaming (evict-first) stores: sim/zq/ids are write-once data
__device__ __forceinline__ void stg_cs_f2(float* p, float2 v) {
    asm volatile("st.global.cs.v2.f32 [%0], {%1,%2};" :: "l"(p), "f"(v.x), "f"(v.y) : "memory");
}
__device__ __forceinline__ void stg_cs_f4(float* p, float4 v) {
    asm volatile("st.global.cs.v4.f32 [%0], {%1,%2,%3,%4};"
                 :: "l"(p), "f"(v.x), "f"(v.y), "f"(v.z), "f"(v.w) : "memory");
}
__device__ __forceinline__ void stg_cs_f1(float* p, float v) {
    asm volatile("st.global.cs.f32 [%0], %1;" :: "l"(p), "f"(v) : "memory");
}
#define MBARRIER_INIT(addr, cnt) \
    asm volatile("mbarrier.init.shared.b64 [%0], %1;" :: "r"(addr), "r"(cnt) : "memory")
#define MBARRIER_EXPECT_TX(addr, tx) \
    asm volatile("mbarrier.arrive.expect_tx.shared.b64 _, [%0], %1;" \
                 :: "r"(addr), "r"(tx) : "memory")
__device__ __forceinline__ void bulk_g2s(uint32_t sdst, const void* gsrc,
                                         uint32_t bytes, uint32_t mbar) {
    asm volatile("cp.async.bulk.shared::cluster.global.mbarrier::complete_tx::bytes "
                 "[%0], [%1], %2, [%3];"
                 :: "r"(sdst), "l"(gsrc), "r"(bytes), "r"(mbar) : "memory");
}
__device__ __forceinline__ void mbar_wait_parity(uint32_t mbar, uint32_t parity) {
    uint32_t done;
    asm volatile(
        "{\n\t.reg .pred p;\n\t"
        "mbarrier.try_wait.parity.acquire.cta.shared::cta.b64 p, [%1], %2;\n\t"
        "selp.b32 %0, 1, 0, p;\n\t}"
        : "=r"(done) : "r"(mbar), "r"(parity) : "memory");
    if (!done) {
        asm volatile(
            "{\n\t.reg .pred P1;\n\t"
            "WL_%=: \n\t"
            "mbarrier.try_wait.parity.acquire.cta.shared::cta.b64 P1, [%0], %1, 0x989680;\n\t"
            "@P1 bra.uni WD_%=;\n\t"
            "bra.uni WL_%=;\n\t"
            "WD_%=: \n\t}"
            :: "r"(mbar), "r"(parity) : "memory");
    }
}

// ---------------- codebook prep: fp16 convert + norms + pre-swizzle ---------
__global__ void prep_e(const float* __restrict__ E) {
    int row  = blockIdx.x * 8 + (threadIdx.x >> 5);
    int lane = threadIdx.x & 31;
    float4 v = reinterpret_cast<const float4*>(E)[(size_t)row * 32 + lane];
    float s = fmaf(v.x, v.x, fmaf(v.y, v.y, fmaf(v.z, v.z, v.w * v.w)));
#pragma unroll
    for (int m = 16; m; m >>= 1) s += __shfl_xor_sync(0xffffffffu, s, m);
    if (lane == 0) { g_ne[row] = s; g_re[row] = rsqrtf(s); }
    __half2 h0 = __halves2half2(__float2half_rn(v.x), __float2half_rn(v.y));
    __half2 h1 = __halves2half2(__float2half_rn(v.z), __float2half_rn(v.w));
    int c  = row >> 6;
    int rr = row & 63;
    int u  = lane >> 1;
    int h  = lane & 1;
    char* dst = (char*)g_Eb + (size_t)c * 16384 + rr * 256
              + (((u ^ (rr & 7)) & 15) << 4) + h * 8;
    uint2 val = make_uint2(*reinterpret_cast<uint32_t*>(&h0),
                           *reinterpret_cast<uint32_t*>(&h1));
    *reinterpret_cast<uint2*>(dst) = val;
}

// ---------------- main fused kernel ----------------
__global__ __launch_bounds__(256, 2)
void vq_main(const float* __restrict__ Z, const float* __restrict__ E,
             float* __restrict__ out) {
    extern __shared__ char sb[];
    const uint32_t sbase = smem_u32(sb);

    const int tid  = threadIdx.x;
    const int lane = tid & 31;
    const int warp = tid >> 5;
    const int wy   = warp >> 2;      // m half (0,1): 32 rows each
    const int wx   = warp & 3;       // n quarter (0..3): 16 codes each
    const int qrow = lane >> 2;
    const int qcol = lane & 3;
    const int m0   = blockIdx.x * BM;

    float* ne_sm = (float*)(sb + NE_OFF);
    float* re_sm = (float*)(sb + RE_OFF);
    float* nz_sm = (float*)(sb + NZ_OFF);
    float* rz_sm = (float*)(sb + RZ_OFF);
    int*   ids_sm = (int*)(sb + IDS_SM);
    float* lt_sm  = (float*)(sb + LT_SM);

    float* zq   = out;
    float* sim  = out + SIM_OFF;
    float* idsf = out + IDSG_OFF;

    // mbarrier init, then kick off bulk loads for chunks 0..2 (ring depth 3)
    if (tid == 0) {
        MBARRIER_INIT(sbase + MBAR_OFF, 1);
        MBARRIER_INIT(sbase + MBAR_OFF + 8, 1);
        MBARRIER_INIT(sbase + MBAR_OFF + 16, 1);
    }
    __syncthreads();
    if (tid == 0) {
#pragma unroll
        for (int c = 0; c < NBUF; ++c) {
            MBARRIER_EXPECT_TX(sbase + MBAR_OFF + c * 8, 16384u);
            bulk_g2s(sbase + B_OFF + c * B_BUF, (const char*)g_Eb + (size_t)c * 16384,
                     16384u, sbase + MBAR_OFF + c * 8);
        }
    }

    // codebook norms into smem
    for (int i = tid; i < KCODE; i += 256) { ne_sm[i] = g_ne[i]; re_sm[i] = g_re[i]; }

    // A prologue: thread = (row, k-quarter); Z read ONCE -> fp32 smem + fp16 A + norm
    {
        const int row = tid >> 2, kh = tid & 3;
        const float4* Zr = reinterpret_cast<const float4*>(
            Z + (size_t)(m0 + row) * 128 + kh * 32);
        float nzp = 0.f;
        uint32_t p1[16];
#pragma unroll
        for (int g = 0; g < 4; ++g) {
            float4 v0 = Zr[2 * g], v1 = Zr[2 * g + 1];
            // keep fp32 copy resident for the exact refine pass
            *(float4*)(sb + ZF_OFF + row * ZF_PITCH + kh * 128 + g * 32)      = v0;
            *(float4*)(sb + ZF_OFF + row * ZF_PITCH + kh * 128 + g * 32 + 16) = v1;
            nzp = fmaf(v0.x, v0.x, fmaf(v0.y, v0.y, fmaf(v0.z, v0.z, fmaf(v0.w, v0.w, nzp))));
            nzp = fmaf(v1.x, v1.x, fmaf(v1.y, v1.y, fmaf(v1.z, v1.z, fmaf(v1.w, v1.w, nzp))));
            __half2 h0 = __halves2half2(__float2half_rn(v0.x), __float2half_rn(v0.y));
            __half2 h1 = __halves2half2(__float2half_rn(v0.z), __float2half_rn(v0.w));
            __half2 h2 = __halves2half2(__float2half_rn(v1.x), __float2half_rn(v1.y));
            __half2 h3 = __halves2half2(__float2half_rn(v1.z), __float2half_rn(v1.w));
            p1[4 * g + 0] = *reinterpret_cast<uint32_t*>(&h0);
            p1[4 * g + 1] = *reinterpret_cast<uint32_t*>(&h1);
            p1[4 * g + 2] = *reinterpret_cast<uint32_t*>(&h2);
            p1[4 * g + 3] = *reinterpret_cast<uint32_t*>(&h3);
        }
#pragma unroll
        for (int q = 0; q < 4; ++q) {
            uint32_t u   = (uint32_t)(kh * 4 + q);
            uint32_t off = (uint32_t)tid / 4u * 256u;   // row*256
            off += (((u ^ (uint32_t)((tid >> 2) & 7))) << 4);
            *(uint4*)(sb + A_OFF + off) = make_uint4(p1[4*q], p1[4*q+1], p1[4*q+2], p1[4*q+3]);
        }
        nzp += __shfl_xor_sync(0xffffffffu, nzp, 1);
        nzp += __shfl_xor_sync(0xffffffffu, nzp, 2);
        if (kh == 0) { nz_sm[row] = nzp; rz_sm[row] = rsqrtf(nzp); }
    }
    __syncthreads();

    // per-thread row constants (4 rows: 2 mfrags x 2 halves)
    float nz4[4], rz4[4];
#pragma unroll
    for (int i = 0; i < 2; ++i)
#pragma unroll
        for (int h = 0; h < 2; ++h) {
            int ml = wy * 32 + i * 16 + qrow + 8 * h;
            nz4[i * 2 + h] = nz_sm[ml];
            rz4[i * 2 + h] = rz_sm[ml];
        }

    // per-thread TOP-2 (dist, idx) per token row
    float bd1[4], bd2[4]; int bi1[4], bi2[4];
#pragma unroll
    for (int i = 0; i < 4; ++i) { bd1[i] = 3.4e38f; bd2[i] = 3.4e38f; bi1[i] = 0; bi2[i] = 0; }

    const int sel = lane >> 3;          // 0..3 (ldmatrix address group)

#pragma unroll 1
    for (int t = 0; t < NCHUNK; ++t) {
        const int buf = t % NBUF;
        const uint32_t mb = sbase + MBAR_OFF + (uint32_t)buf * 8;
        mbar_wait_parity(mb, (uint32_t)((t / NBUF) & 1));
        const uint32_t Bb = sbase + B_OFF + (uint32_t)buf * B_BUF;

        float acc[2][2][4];
#pragma unroll
        for (int i = 0; i < 2; ++i)
#pragma unroll
            for (int nf = 0; nf < 2; ++nf)
#pragma unroll
                for (int q = 0; q < 4; ++q) acc[i][nf][q] = 0.f;

        // single-product fp16 GEMM: z1 . e1
#pragma unroll
        for (int kk = 0; kk < 8; ++kk) {
            const uint32_t cu = (uint32_t)(kk * 2 + (sel >> 1));
            uint32_t a[2][4];
#pragma unroll
            for (int i = 0; i < 2; ++i) {
                int r = wy * 32 + i * 16 + (sel & 1) * 8 + (lane & 7);
                uint32_t addr = sbase + A_OFF + (uint32_t)r * 256u
                              + (((cu ^ (uint32_t)(r & 7))) << 4);
                ldsm_x4(a[i][0], a[i][1], a[i][2], a[i][3], addr);
            }
            int r = wx * 16 + (sel & 1) * 8 + (lane & 7);
            uint32_t addr = Bb + (uint32_t)r * 256u + (((cu ^ (uint32_t)(r & 7))) << 4);
            uint32_t b0, b1, b2, b3;
            ldsm_x4(b0, b1, b2, b3, addr);
            uint32_t bf0[2] = { b0, b2 };
            uint32_t bf1[2] = { b1, b3 };
#pragma unroll
            for (int i = 0; i < 2; ++i) {
                mma_f16(acc[i][0], a[i], bf0);
                mma_f16(acc[i][1], a[i], bf1);
            }
        }
        __syncthreads();   // ONLY sync per chunk: B(t) consumed by all warps
        if (t + NBUF < NCHUNK && tid == 0) {  // refill freed buffer with chunk t+3
            MBARRIER_EXPECT_TX(mb, 16384u);
            bulk_g2s(Bb, (const char*)g_Eb + (size_t)(t + NBUF) * 16384, 16384u, mb);
        }

        // ---- epilogue: dist -> top-2 + streaming sim stores (no barrier) ----
        const int nbase = t * BN + wx * 16;
#pragma unroll
        for (int nf = 0; nf < 2; ++nf) {
            const int nc = nbase + nf * 8 + qcol * 2;
            float2 ne2 = *reinterpret_cast<const float2*>(ne_sm + nc);
            float2 re2 = *reinterpret_cast<const float2*>(re_sm + nc);
#pragma unroll
            for (int i = 0; i < 2; ++i) {
#pragma unroll
                for (int h = 0; h < 2; ++h) {
                    const int idx = i * 2 + h;
                    const float d0 = acc[i][nf][h * 2 + 0];
                    const float d1 = acc[i][nf][h * 2 + 1];
                    float dd0 = fmaf(-2.f, d0, nz4[idx]) + ne2.x;
                    float dd1 = fmaf(-2.f, d1, nz4[idx]) + ne2.y;
                    if (dd0 < bd2[idx]) {
                        if (dd0 < bd1[idx]) { bd2[idx]=bd1[idx]; bi2[idx]=bi1[idx];
                                              bd1[idx]=dd0; bi1[idx]=nc; }
                        else                { bd2[idx]=dd0; bi2[idx]=nc; }
                    }
                    if (dd1 < bd2[idx]) {
                        if (dd1 < bd1[idx]) { bd2[idx]=bd1[idx]; bi2[idx]=bi1[idx];
                                              bd1[idx]=dd1; bi1[idx]=nc + 1; }
                        else                { bd2[idx]=dd1; bi2[idx]=nc + 1; }
                    }
                    const int ml = wy * 32 + i * 16 + qrow + 8 * h;
                    float2 sv = make_float2(d0 * rz4[idx] * re2.x,
                                            d1 * rz4[idx] * re2.y);
                    stg_cs_f2(sim + (size_t)(m0 + ml) * 1024 + nc, sv);
                }
            }
        }
    }

    // ---- dump per-thread top-2 candidates into dead A region ----
    float* redD = (float*)(sb + REDD_OFF);
    int*   redI = (int*)(sb + REDI_OFF);
#pragma unroll
    for (int idx = 0; idx < 4; ++idx) {
        int i = idx >> 1, h = idx & 1;
        int tok = wy * 32 + i * 16 + qrow + 8 * h;
        int base = tok * 32 + (wx * 4 + qcol) * 2;
        redD[base] = bd1[idx];     redI[base] = bi1[idx];
        redD[base + 1] = bd2[idx]; redI[base + 1] = bi2[idx];
    }
    __syncthreads();

    // ---- exact fp32 refine: one thread per token (Z fp32 already resident) ----
    if (tid < BM) {
        const int tok = tid;
        float m1 = 3.4e38f;
#pragma unroll
        for (int e = 0; e < 32; ++e) m1 = fminf(m1, redD[tok * 32 + e]);
        const float thr = m1 + MARGIN;
        const float nzt = nz_sm[tok];
        const char* zf = sb + ZF_OFF + tok * ZF_PITCH;
        float bestd = 3.4e38f; int besti = KCODE;
        for (int e = 0; e < 32; ++e) {
            if (redD[tok * 32 + e] <= thr) {
                const int id = redI[tok * 32 + e];
                const float4* Er = reinterpret_cast<const float4*>(E) + (size_t)id * 32;
                float dot = 0.f;
#pragma unroll
                for (int q = 0; q < 32; ++q) {
                    float4 a = *(const float4*)(zf + q * 16);
                    float4 b = Er[q];
                    dot = fmaf(a.x, b.x, fmaf(a.y, b.y, fmaf(a.z, b.z, fmaf(a.w, b.w, dot))));
                }
                float de = fmaf(-2.f, dot, nzt) + ne_sm[id];   // reference association order
                if (de < bestd || (de == bestd && id < besti)) { bestd = de; besti = id; }
            }
        }
        ids_sm[tok] = besti;
        stg_cs_f1(idsf + m0 + tok, (float)besti);
        lt_sm[tok] = sqrtf(fmaxf(bestd, 0.f));   // ||z - z_q||^2 == dist_min exactly
    }
    __syncthreads();

    // z_q gather (codebook is L2-resident), streaming stores
    const float4* E4 = reinterpret_cast<const float4*>(E);
#pragma unroll
    for (int rr = 0; rr < 8; ++rr) {
        int ml = warp * 8 + rr;
        int id = ids_sm[ml];
        stg_cs_f4(zq + ((size_t)(m0 + ml) * 32 + lane) * 4, E4[(size_t)id * 32 + lane]);
    }

    // deterministic per-block loss partial (fixed serial order)
    if (tid == 0) {
        float s = 0.f;
        for (int i = 0; i < BM; ++i) s += lt_sm[i];
        g_partial[blockIdx.x] = s;
    }

    // ---- merged loss reduction: last CTA sums all partials (fixed tree) ----
    __shared__ int is_last;
    __threadfence();
    if (tid == 0) {
        unsigned old = atomicAdd(&g_done, 1u);
        is_last = (old == GRID_MAIN - 1) ? 1 : 0;
    }
    __syncthreads();
    if (is_last) {
        __threadfence();
        float* red = (float*)(sb + REDD_OFF);   // reuse candidate area
        float s = g_partial[tid] + g_partial[tid + 256]
                + g_partial[tid + 512] + g_partial[tid + 768];
        red[tid] = s;
        __syncthreads();
#pragma unroll
        for (int st = 128; st > 0; st >>= 1) {
            if (tid < st) red[tid] += red[tid + st];
            __syncthreads();
        }
        if (tid == 0) {
            out[LOSS_OFF] = 1.25f * (red[0] * (1.f / 65536.f));
            g_done = 0;   // reset for the next graph replay
        }
    }
}

extern "C" void kernel_launch(void* const* d_in, const int* in_sizes, int n_in,
                              void* d_out, int out_size) {
    (void)in_sizes; (void)n_in; (void)out_size;
    const float* Z = (const float*)d_in[0];   // z_e            [65536, 128]
    const float* E = (const float*)d_in[1];   // vecs_embedding [1024, 128]
    float* out = (float*)d_out;

    cudaFuncSetAttribute((const void*)vq_main,
                         cudaFuncAttributeMaxDynamicSharedMemorySize, SMEM_BYTES);

    prep_e<<<KCODE / 8, 256>>>(E);
    vq_main<<<GRID_MAIN, 256, SMEM_BYTES>>>(Z, E, out);
}

// round 15
// speedup vs baseline: 1.0427x; 1.0342x over previous
#include <cuda_runtime.h>
#include <cuda_fp16.h>
#include <math.h>
#include <stdint.h>

// ---------------- problem constants ----------------
#define M_TOK   65536
#define KCODE   1024
#define BM      64            // tokens per CTA
#define BN      64            // codes per chunk
#define NCHUNK  16
#define GRID_MAIN 1024
#define MARGIN  0.25f

// Output layout (floats): [z_q | similarity | ids | loss]
#define SIM_OFF   8388608ULL
#define IDSG_OFF  75497472ULL
#define LOSS_OFF  75563008ULL

// ---------------- smem layout (byte offsets) ----------------
#define ZF_PITCH   528            // 33x16B: 4-way (not 32-way) conflicts in refine
#define ZF_OFF     0              // fp32 Z tile: 64 x 528 = 33792 (live whole kernel)
#define A_OFF      33792          // z fp16: 64 rows x 256B = 16384 (dead after loop)
#define NE_OFF     50176          // 4096
#define RE_OFF     54272          // 4096
#define NZ_OFF     58368          // 256
#define RZ_OFF     58624          // 256
#define IDS_SM     58880          // 256
#define LT_SM      59136          // 256
#define SMEM_BYTES 59392          // x3 CTAs = 178176 <= 228KB carveout

// post-loop overlays (A region dead after main loop)
#define REDD_OFF   33792          // 64 tok x 32 cand dists = 8192
#define REDI_OFF   41984          // 64 tok x 32 cand idx   = 8192

// ---------------- device scratch ----------------
// fp16 codebook in EXACT mma-fragment order:
//   g_Eb[((chunk*8 + kk)*8 + nblock)*32 + lane] = { b0, b1 } (uint2)
// where for lane T: n = nblock*8 + T/4, k0 = kk*16 + (T%4)*2,
//   b0 = halves (k0, k0+1) of code n,  b1 = halves (k0+8, k0+9).
// One coalesced LDG.64 per warp per (kk, nblock) == the standard B fragment.
__device__ __align__(16) uint2 g_Eb[NCHUNK * 8 * 8 * 32];
__device__ float g_ne[KCODE];
__device__ float g_re[KCODE];
__device__ float g_partial[GRID_MAIN];
__device__ unsigned g_done = 0;   // last-CTA counter (self-resetting each pass)

// ---------------- PTX helpers (baseline ISA only) ----------------
__device__ __forceinline__ uint32_t smem_u32(const void* p) {
    uint32_t a;
    asm("{ .reg .u64 t; cvta.to.shared.u64 t, %1; cvt.u32.u64 %0, t; }" : "=r"(a) : "l"(p));
    return a;
}
__device__ __forceinline__ void ldsm_x4(uint32_t& r0, uint32_t& r1, uint32_t& r2, uint32_t& r3,
                                        uint32_t addr) {
    asm volatile("ldmatrix.sync.aligned.m8n8.x4.shared.b16 {%0,%1,%2,%3}, [%4];"
                 : "=r"(r0), "=r"(r1), "=r"(r2), "=r"(r3) : "r"(addr));
}
__device__ __forceinline__ void mma_f16(float* c, const uint32_t* a, const uint32_t* b) {
    asm volatile("mma.sync.aligned.m16n8k16.row.col.f32.f16.f16.f32 "
                 "{%0,%1,%2,%3}, {%4,%5,%6,%7}, {%8,%9}, {%0,%1,%2,%3};"
                 : "+f"(c[0]), "+f"(c[1]), "+f"(c[2]), "+f"(c[3])
                 : "r"(a[0]), "r"(a[1]), "r"(a[2]), "r"(a[3]), "r"(b[0]), "r"(b[1]));
}
// streaming (evict-first) stores: sim/zq/ids are write-once data
__device__ __forceinline__ void stg_cs_f2(float* p, float2 v) {
    asm volatile("st.global.cs.v2.f32 [%0], {%1,%2};" :: "l"(p), "f"(v.x), "f"(v.y) : "memory");
}
__device__ __forceinline__ void stg_cs_f4(float* p, float4 v) {
    asm volatile("st.global.cs.v4.f32 [%0], {%1,%2,%3,%4};"
                 :: "l"(p), "f"(v.x), "f"(v.y), "f"(v.z), "f"(v.w) : "memory");
}
__device__ __forceinline__ void stg_cs_f1(float* p, float v) {
    asm volatile("st.global.cs.f32 [%0], %1;" :: "l"(p), "f"(v) : "memory");
}

// ---------------- codebook prep: fp16 convert + norms + fragment order ------
__global__ void prep_e(const float* __restrict__ E) {
    int row  = blockIdx.x * 8 + (threadIdx.x >> 5);   // global code id
    int lane = threadIdx.x & 31;
    float4 v = reinterpret_cast<const float4*>(E)[(size_t)row * 32 + lane];
    float s = fmaf(v.x, v.x, fmaf(v.y, v.y, fmaf(v.z, v.z, v.w * v.w)));
#pragma unroll
    for (int m = 16; m; m >>= 1) s += __shfl_xor_sync(0xffffffffu, s, m);
    if (lane == 0) { g_ne[row] = s; g_re[row] = rsqrtf(s); }

    __half2 hA = __halves2half2(__float2half_rn(v.x), __float2half_rn(v.y));
    __half2 hB = __halves2half2(__float2half_rn(v.z), __float2half_rn(v.w));
    uint32_t wA = *reinterpret_cast<uint32_t*>(&hA);   // halves 4L, 4L+1
    uint32_t wB = *reinterpret_cast<uint32_t*>(&hB);   // halves 4L+2, 4L+3

    const int c    = row >> 6;        // chunk
    const int nloc = row & 63;
    const int nb   = nloc >> 3;       // n-block
    const int Tn   = nloc & 7;        // lane group within block
    uint32_t* Eb32 = reinterpret_cast<uint32_t*>(g_Eb);
#pragma unroll
    for (int j2 = 0; j2 < 2; ++j2) {
        int h0 = 4 * lane + j2 * 2;           // first half index of this word
        int kk = h0 >> 4;
        int hh = h0 & 15;
        int b  = hh >> 3;                     // 0 = b0 word, 1 = b1 word
        int tk = (hh & 7) >> 1;               // T % 4
        int T  = Tn * 4 + tk;
        int idx = (((c * 8 + kk) * 8 + nb) * 32 + T) * 2 + b;
        Eb32[idx] = j2 ? wB : wA;
    }
}

// ---------------- main fused kernel (NO intra-loop synchronization) ---------
__global__ __launch_bounds__(256, 3)
void vq_main(const float* __restrict__ Z, const float* __restrict__ E,
             float* __restrict__ out) {
    extern __shared__ char sb[];
    const uint32_t sbase = smem_u32(sb);

    const int tid  = threadIdx.x;
    const int lane = tid & 31;
    const int warp = tid >> 5;
    const int wy   = warp >> 2;      // m half (0,1): 32 rows each
    const int wx   = warp & 3;       // n quarter (0..3): 16 codes each
    const int qrow = lane >> 2;
    const int qcol = lane & 3;
    const int m0   = blockIdx.x * BM;

    float* ne_sm = (float*)(sb + NE_OFF);
    float* re_sm = (float*)(sb + RE_OFF);
    float* nz_sm = (float*)(sb + NZ_OFF);
    float* rz_sm = (float*)(sb + RZ_OFF);
    int*   ids_sm = (int*)(sb + IDS_SM);
    float* lt_sm  = (float*)(sb + LT_SM);

    float* zq   = out;
    float* sim  = out + SIM_OFF;
    float* idsf = out + IDSG_OFF;

    // codebook norms into smem
    for (int i = tid; i < KCODE; i += 256) { ne_sm[i] = g_ne[i]; re_sm[i] = g_re[i]; }

    // A prologue: thread = (row, k-quarter); Z read ONCE -> fp32 smem + fp16 A + norm
    {
        const int row = tid >> 2, kh = tid & 3;
        const float4* Zr = reinterpret_cast<const float4*>(
            Z + (size_t)(m0 + row) * 128 + kh * 32);
        float nzp = 0.f;
        uint32_t p1[16];
#pragma unroll
        for (int g = 0; g < 4; ++g) {
            float4 v0 = Zr[2 * g], v1 = Zr[2 * g + 1];
            *(float4*)(sb + ZF_OFF + row * ZF_PITCH + kh * 128 + g * 32)      = v0;
            *(float4*)(sb + ZF_OFF + row * ZF_PITCH + kh * 128 + g * 32 + 16) = v1;
            nzp = fmaf(v0.x, v0.x, fmaf(v0.y, v0.y, fmaf(v0.z, v0.z, fmaf(v0.w, v0.w, nzp))));
            nzp = fmaf(v1.x, v1.x, fmaf(v1.y, v1.y, fmaf(v1.z, v1.z, fmaf(v1.w, v1.w, nzp))));
            __half2 h0 = __halves2half2(__float2half_rn(v0.x), __float2half_rn(v0.y));
            __half2 h1 = __halves2half2(__float2half_rn(v0.z), __float2half_rn(v0.w));
            __half2 h2 = __halves2half2(__float2half_rn(v1.x), __float2half_rn(v1.y));
            __half2 h3 = __halves2half2(__float2half_rn(v1.z), __float2half_rn(v1.w));
            p1[4 * g + 0] = *reinterpret_cast<uint32_t*>(&h0);
            p1[4 * g + 1] = *reinterpret_cast<uint32_t*>(&h1);
            p1[4 * g + 2] = *reinterpret_cast<uint32_t*>(&h2);
            p1[4 * g + 3] = *reinterpret_cast<uint32_t*>(&h3);
        }
#pragma unroll
        for (int q = 0; q < 4; ++q) {
            uint32_t u   = (uint32_t)(kh * 4 + q);
            uint32_t off = (uint32_t)row * 256u + (((u ^ (uint32_t)(row & 7))) << 4);
            *(uint4*)(sb + A_OFF + off) = make_uint4(p1[4*q], p1[4*q+1], p1[4*q+2], p1[4*q+3]);
        }
        nzp += __shfl_xor_sync(0xffffffffu, nzp, 1);
        nzp += __shfl_xor_sync(0xffffffffu, nzp, 2);
        if (kh == 0) { nz_sm[row] = nzp; rz_sm[row] = rsqrtf(nzp); }
    }
    __syncthreads();   // the ONLY pre-loop barrier; none inside the loop

    // per-thread row constants (4 rows: 2 mfrags x 2 halves)
    float nz4[4], rz4[4];
#pragma unroll
    for (int i = 0; i < 2; ++i)
#pragma unroll
        for (int h = 0; h < 2; ++h) {
            int ml = wy * 32 + i * 16 + qrow + 8 * h;
            nz4[i * 2 + h] = nz_sm[ml];
            rz4[i * 2 + h] = rz_sm[ml];
        }

    // per-thread TOP-2 (dist, idx) per token row
    float bd1[4], bd2[4]; int bi1[4], bi2[4];
#pragma unroll
    for (int i = 0; i < 4; ++i) { bd1[i] = 3.4e38f; bd2[i] = 3.4e38f; bi1[i] = 0; bi2[i] = 0; }

    const int sel = lane >> 3;          // 0..3 (ldmatrix address group)
    const uint2* __restrict__ Eb = g_Eb;

#pragma unroll 1
    for (int t = 0; t < NCHUNK; ++t) {
        float acc[2][2][4];
#pragma unroll
        for (int i = 0; i < 2; ++i)
#pragma unroll
            for (int nf = 0; nf < 2; ++nf)
#pragma unroll
                for (int q = 0; q < 4; ++q) acc[i][nf][q] = 0.f;

        // single-product fp16 GEMM: A from smem (LDSM), B fragments via LDG
#pragma unroll
        for (int kk = 0; kk < 8; ++kk) {
            const uint32_t cu = (uint32_t)(kk * 2 + (sel >> 1));
            uint32_t a[2][4];
#pragma unroll
            for (int i = 0; i < 2; ++i) {
                int r = wy * 32 + i * 16 + (sel & 1) * 8 + (lane & 7);
                uint32_t addr = sbase + A_OFF + (uint32_t)r * 256u
                              + (((cu ^ (uint32_t)(r & 7))) << 4);
                ldsm_x4(a[i][0], a[i][1], a[i][2], a[i][3], addr);
            }
#pragma unroll
            for (int nf = 0; nf < 2; ++nf) {
                uint2 w = __ldg(&Eb[((t * 8 + kk) * 8 + wx * 2 + nf) * 32 + lane]);
                uint32_t bf[2] = { w.x, w.y };
                mma_f16(acc[0][nf], a[0], bf);
                mma_f16(acc[1][nf], a[1], bf);
            }
        }

        // ---- epilogue: dist -> top-2 + streaming sim stores (no barrier) ----
        const int nbase = t * BN + wx * 16;
#pragma unroll
        for (int nf = 0; nf < 2; ++nf) {
            const int nc = nbase + nf * 8 + qcol * 2;
            float2 ne2 = *reinterpret_cast<const float2*>(ne_sm + nc);
            float2 re2 = *reinterpret_cast<const float2*>(re_sm + nc);
#pragma unroll
            for (int i = 0; i < 2; ++i) {
#pragma unroll
                for (int h = 0; h < 2; ++h) {
                    const int idx = i * 2 + h;
                    const float d0 = acc[i][nf][h * 2 + 0];
                    const float d1 = acc[i][nf][h * 2 + 1];
                    float dd0 = fmaf(-2.f, d0, nz4[idx]) + ne2.x;
                    float dd1 = fmaf(-2.f, d1, nz4[idx]) + ne2.y;
                    if (dd0 < bd2[idx]) {
                        if (dd0 < bd1[idx]) { bd2[idx]=bd1[idx]; bi2[idx]=bi1[idx];
                                              bd1[idx]=dd0; bi1[idx]=nc; }
                        else                { bd2[idx]=dd0; bi2[idx]=nc; }
                    }
                    if (dd1 < bd2[idx]) {
                        if (dd1 < bd1[idx]) { bd2[idx]=bd1[idx]; bi2[idx]=bi1[idx];
                                              bd1[idx]=dd1; bi1[idx]=nc + 1; }
                        else                { bd2[idx]=dd1; bi2[idx]=nc + 1; }
                    }
                    const int ml = wy * 32 + i * 16 + qrow + 8 * h;
                    float2 sv = make_float2(d0 * rz4[idx] * re2.x,
                                            d1 * rz4[idx] * re2.y);
                    stg_cs_f2(sim + (size_t)(m0 + ml) * 1024 + nc, sv);
                }
            }
        }
    }

    // ---- all warps done: A region is dead; dump top-2 candidates there ----
    __syncthreads();
    float* redD = (float*)(sb + REDD_OFF);
    int*   redI = (int*)(sb + REDI_OFF);
#pragma unroll
    for (int idx = 0; idx < 4; ++idx) {
        int i = idx >> 1, h = idx & 1;
        int tok = wy * 32 + i * 16 + qrow + 8 * h;
        int base = tok * 32 + (wx * 4 + qcol) * 2;
        redD[base] = bd1[idx];     redI[base] = bi1[idx];
        redD[base + 1] = bd2[idx]; redI[base + 1] = bi2[idx];
    }
    __syncthreads();

    // ---- exact fp32 refine: one thread per token (Z fp32 resident) ----
    if (tid < BM) {
        const int tok = tid;
        float m1 = 3.4e38f;
#pragma unroll
        for (int e = 0; e < 32; ++e) m1 = fminf(m1, redD[tok * 32 + e]);
        const float thr = m1 + MARGIN;
        const float nzt = nz_sm[tok];
        const char* zf = sb + ZF_OFF + tok * ZF_PITCH;
        float bestd = 3.4e38f; int besti = KCODE;
        for (int e = 0; e < 32; ++e) {
            if (redD[tok * 32 + e] <= thr) {
                const int id = redI[tok * 32 + e];
                const float4* Er = reinterpret_cast<const float4*>(E) + (size_t)id * 32;
                float dot = 0.f;
#pragma unroll
                for (int q = 0; q < 32; ++q) {
                    float4 a = *(const float4*)(zf + q * 16);
                    float4 b = Er[q];
                    dot = fmaf(a.x, b.x, fmaf(a.y, b.y, fmaf(a.z, b.z, fmaf(a.w, b.w, dot))));
                }
                float de = fmaf(-2.f, dot, nzt) + ne_sm[id];   // reference association order
                if (de < bestd || (de == bestd && id < besti)) { bestd = de; besti = id; }
            }
        }
        ids_sm[tok] = besti;
        stg_cs_f1(idsf + m0 + tok, (float)besti);
        lt_sm[tok] = sqrtf(fmaxf(bestd, 0.f));   // ||z - z_q||^2 == dist_min exactly
    }
    __syncthreads();

    // z_q gather (codebook is L2-resident), streaming stores
    const float4* E4 = reinterpret_cast<const float4*>(E);
#pragma unroll
    for (int rr = 0; rr < 8; ++rr) {
        int ml = warp * 8 + rr;
        int id = ids_sm[ml];
        stg_cs_f4(zq + ((size_t)(m0 + ml) * 32 + lane) * 4, E4[(size_t)id * 32 + lane]);
    }

    // deterministic per-block loss partial (fixed serial order)
    if (tid == 0) {
        float s = 0.f;
        for (int i = 0; i < BM; ++i) s += lt_sm[i];
        g_partial[blockIdx.x] = s;
    }

    // ---- merged loss reduction: last CTA sums all partials (fixed tree) ----
    __shared__ int is_last;
    __threadfence();
    if (tid == 0) {
        unsigned old = atomicAdd(&g_done, 1u);
        is_last = (old == GRID_MAIN - 1) ? 1 : 0;
    }
    __syncthreads();
    if (is_last) {
        __threadfence();
        float* red = (float*)(sb + REDD_OFF);   // reuse candidate area
        float s = g_partial[tid] + g_partial[tid + 256]
                + g_partial[tid + 512] + g_partial[tid + 768];
        red[tid] = s;
        __syncthreads();
#pragma unroll
        for (int st = 128; st > 0; st >>= 1) {
            if (tid < st) red[tid] += red[tid + st];
            __syncthreads();
        }
        if (tid == 0) {
            out[LOSS_OFF] = 1.25f * (red[0] * (1.f / 65536.f));
            g_done = 0;   // reset for the next graph replay
        }
    }
}

extern "C" void kernel_launch(void* const* d_in, const int* in_sizes, int n_in,
                              void* d_out, int out_size) {
    (void)in_sizes; (void)n_in; (void)out_size;
    const float* Z = (const float*)d_in[0];   // z_e            [65536, 128]
    const float* E = (const float*)d_in[1];   // vecs_embedding [1024, 128]
    float* out = (float*)d_out;

    cudaFuncSetAttribute((const void*)vq_main,
                         cudaFuncAttributeMaxDynamicSharedMemorySize, SMEM_BYTES);

    prep_e<<<KCODE / 8, 256>>>(E);
    vq_main<<<GRID_MAIN, 256, SMEM_BYTES>>>(Z, E, out);
}